// round 11
// baseline (speedup 1.0000x reference)
#include <cuda_runtime.h>

#define FULL 0xffffffffu

static constexpr int S = 256;
static constexpr int STR1 = 269;            // padded emb row: 6 + 256 + 6 (+1 spare)
static constexpr int L1_LEN = 262, K1 = 131;
static constexpr int STR2 = 140;            // padded A row: 4 + 131 + 4 (+1 spare)
static constexpr int NTHREADS = 256;
static constexpr int NWORKERS = 148 * 4;    // persistent grid: 4 CTAs/SM, all resident
static constexpr int NITEMS = 512 * 8;      // item = (batch, 2-rpp half-slice)

static constexpr int ROWS_IN = 8;                       // emb rows per item
static constexpr int ROWS_A  = 32;                      // A rows per item
static constexpr int OFF_A  = ROWS_IN * STR1;           // 2152 floats
static constexpr int SMEM_FLOATS = OFF_A + ROWS_A * STR2;   // 6632
static constexpr int SMEM_BYTES  = SMEM_FLOATS * 4;         // 26528 B -> 4 CTAs/SM easy

__device__ float g_T2[512 * 1024];          // cross-kernel feature scratch

// Monotone float -> uint key (total order). Inverse restores the exact float.
__device__ __forceinline__ unsigned fkey(float f) {
    unsigned b = __float_as_uint(f);
    return (b & 0x80000000u) ? ~b : (b | 0x80000000u);
}
__device__ __forceinline__ float funkey(unsigned u) {
    unsigned b = (u & 0x80000000u) ? (u & 0x7fffffffu) : ~u;
    return __uint_as_float(b);
}

// Fast tanh: abs error ~1e-6 (applied only AFTER selection -> no selection impact)
__device__ __forceinline__ float tanh_fast(float x) {
    float ax = fabsf(x);
    float t = __expf(-2.f * ax);
    float r = __fdividef(1.f - t, 1.f + t);
    return copysignf(r, x);
}

__device__ __forceinline__ int iscan(int v, int lane) {
#pragma unroll
    for (int d = 1; d < 32; d <<= 1) {
        int n = __shfl_up_sync(FULL, v, d);
        if (lane >= d) v += n;
    }
    return v;
}

__device__ __forceinline__ unsigned long long umax64(unsigned long long a, unsigned long long b) { return a > b ? a : b; }
__device__ __forceinline__ unsigned long long umin64(unsigned long long a, unsigned long long b) { return a < b ? a : b; }

// Warp-collective order-preserving top-k on keys u[] (blocked across lanes,
// invalid slots key 0). Writes k tanh'd values in original index order;
// jax.lax.top_k tie semantics (earliest index). 2-bit radix bisection with
// packed counts and early exit on exact separation.
template <int NV>
__device__ __forceinline__ void topk_write_keys(const unsigned* u, int k, float* outrow, int lane) {
    unsigned thr = 0;
    bool clean = false;
#pragma unroll 1
    for (int bit = 31; bit >= 1; bit -= 2) {
        unsigned c1 = thr | (1u << (bit - 1));
        unsigned c2 = thr | (2u << (bit - 1));
        unsigned c3 = thr | (3u << (bit - 1));
        unsigned p = 0;
#pragma unroll
        for (int j = 0; j < NV; j++) {
            p += (u[j] >= c1);
            p += (u[j] >= c2) ? 1024u : 0u;
            p += (u[j] >= c3) ? (1024u * 1024u) : 0u;
        }
        p = __reduce_add_sync(FULL, p);
        int n1 = p & 1023, n2 = (p >> 10) & 1023, n3 = p >> 20;
        int cc;
        if (n3 >= k)      { thr = c3; cc = n3; }
        else if (n2 >= k) { thr = c2; cc = n2; }
        else if (n1 >= k) { thr = c1; cc = n1; }
        else              { cc = -1; }
        if (cc == k) { clean = true; break; }
    }

    if (clean) {
        int kc = 0;
#pragma unroll
        for (int j = 0; j < NV; j++) kc += (u[j] >= thr);
        int pos = iscan(kc, lane) - kc;
#pragma unroll
        for (int j = 0; j < NV; j++)
            if (u[j] >= thr) outrow[pos++] = tanh_fast(funkey(u[j]));
        return;
    }

    // Full-resolution tie path: thr is the exact k-th largest key.
    int gt = 0, eq = 0;
#pragma unroll
    for (int j = 0; j < NV; j++) { gt += (u[j] > thr); eq += (u[j] == thr); }
    int gt_tot = __reduce_add_sync(FULL, gt);
    int extra = k - gt_tot;
    int eq_excl = iscan(eq, lane) - eq;
    int myq = extra - eq_excl;
    myq = myq < 0 ? 0 : (myq > eq ? eq : myq);
    int kc = gt + myq;
    int pos = iscan(kc, lane) - kc;
    int used = 0;
#pragma unroll
    for (int j = 0; j < NV; j++) {
        bool keep = (u[j] > thr);
        if (!keep && u[j] == thr && used < myq) { keep = true; used++; }
        if (keep) outrow[pos++] = tanh_fast(funkey(u[j]));
    }
}

// ---------------------------------------------------------------------------
// Main kernel: persistent workers. grid = 592, block = 256.
// Item it = (b, h): b = it>>3, h = it&7. Covers rpp in {2h, 2h+1}:
//   emb rows [8h, 8h+8), conv1-fold channels [32h, 32h+32),
//   conv2-fold channels [32h, 32h+32).
// ---------------------------------------------------------------------------
__global__ void __launch_bounds__(NTHREADS, 4) dcnn_main(
    const int* __restrict__ x, const float* __restrict__ emb,
    const float* __restrict__ w1, const float* __restrict__ b1,
    const float* __restrict__ w2, const float* __restrict__ b2)
{
    extern __shared__ float sm[];
    float* sm_in = sm;            // [8][269]  padded embedded input slice
    float* sm_A  = sm + OFF_A;    // [32][140] padded layer-1 output slice

    const int tid = threadIdx.x, lane = tid & 31, wid = tid >> 5;

#pragma unroll 1
    for (int it = blockIdx.x; it < NITEMS; it += NWORKERS) {
        const int b = it >> 3, h = it & 7;

        // ---- zero ONLY the pad cells (conv zero-padding) ----
        for (int i = tid; i < 392; i += NTHREADS) {
            if (i < 104) {                       // sm_in pads: cols 0..5, 262..268
                int r = i / 13, c = i % 13;
                sm_in[r * STR1 + (c < 6 ? c : 256 + c)] = 0.f;
            } else {                             // sm_A pads: cols 0..3, 135..139
                int j = i - 104;
                int r = j / 9, c = j % 9;
                sm_A[r * STR2 + (c < 4 ? c : 131 + c)] = 0.f;
            }
        }

        // ---- embedding gather for this slice, transposed, padded by 6 ----
        const int* xb = x + b * S;
        const int dbase = 8 * h;
        for (int i = tid; i < S * ROWS_IN; i += NTHREADS) {
            int s = i >> 3, dl = i & 7;
            sm_in[dl * STR1 + 6 + s] = emb[(long)xb[s] * 64 + dbase + dl];
        }
        __syncthreads();

        // ---- Phase 2: conv1 (K=7) + fold(pairs) + top-131 + tanh ----
        // Warp w handles local channels 4w..4w+3 (all same rp): stage the two
        // input rows to registers ONCE, reuse across the 4 f-channels.
        // Association matches XLA: complete ascending-k chain per conv channel,
        // bias per channel, fold adds the two finished results.
        {
            const int rp_l = wid >> 1;               // 0..3
            const int fb   = (wid & 1) * 4;
            const int rp_g = 4 * h + rp_l;
            const float* inA = sm_in + (2 * rp_l) * STR1;
            const float* inB = inA + STR1;

            const int t0 = lane * 9;                 // blocked: preserves index order
            float a[15], bbv[15];
#pragma unroll
            for (int i = 0; i < 15; i++) {
                int idx = t0 + i; bool ok = idx < 268;
                a[i]   = ok ? inA[idx] : 0.f;
                bbv[i] = ok ? inB[idx] : 0.f;
            }

#pragma unroll 1
            for (int fj = 0; fj < 4; fj++) {
                const int f  = fb + fj;
                const int o0 = 2 * rp_g * 8 + f, o1 = o0 + 8;
                float wA[7], wB[7];
#pragma unroll
                for (int k = 0; k < 7; k++) { wA[k] = w1[o0 * 7 + k]; wB[k] = w1[o1 * 7 + k]; }
                const float bA = b1[o0], bB = b1[o1];

                unsigned u[9];
#pragma unroll
                for (int j = 0; j < 9; j++) {
                    float sA = 0.f, sB = 0.f;
#pragma unroll
                    for (int k = 0; k < 7; k++) {    // two independent ascending chains
                        sA = fmaf(wA[k], a[j + k], sA);
                        sB = fmaf(wB[k], bbv[j + k], sB);
                    }
                    float acc = (sA + bA) + (sB + bB);   // fold after completed channels
                    u[j] = (t0 + j < L1_LEN) ? fkey(acc) : 0u;
                }
                topk_write_keys<9>(u, K1, sm_A + (rp_l * 8 + f) * STR2 + 4, lane);
            }
        }
        __syncthreads();

        // ---- Phase 3: conv2 (K=5) + fold + top-4 + tanh ----
        // Thread-per-(channel, chunk): 32 channels x 8 chunks of 17 (last 16).
        {
            const int ci2_l = (wid << 2) | (lane >> 3);   // 0..31
            const int chunk = lane & 7;                    // 0..7
            const int rpp_l = ci2_l >> 4, f2 = ci2_l & 15;
            const int rpp_g = 2 * h + rpp_l;
            const int ci2_g = rpp_g * 16 + f2;
            const int o0 = 2 * rpp_g * 16 + f2, o1 = o0 + 16;
            const float bA = b2[o0], bB = b2[o1];
            const float* W0 = w2 + o0 * 40;
            const float* W1 = w2 + o1 * 40;
            const float* rows0 = sm_A + (16 * rpp_l) * STR2;
            const float* rows1 = rows0 + 8 * STR2;

            const int p0 = chunk * 17;
            const int np = (chunk == 7) ? 16 : 17;

            unsigned long long m0 = 0, m1 = 0, m2 = 0, m3 = 0;

#pragma unroll 1
            for (int pb = 0; pb < 17; pb += 7) {
                const int base = p0 + pb;
                const int nn = min(7, np - pb);
                float accA[7] = {0, 0, 0, 0, 0, 0, 0};
                float accB[7] = {0, 0, 0, 0, 0, 0, 0};
                float win[11];
#pragma unroll
                for (int i = 0; i < 8; i++) {        // channel A: (i asc, k2 asc) chain
                    const float* row = rows0 + i * STR2;
#pragma unroll
                    for (int q = 0; q < 11; q++)
                        win[q] = (q < 7 || base + q < 140) ? row[base + q] : 0.f;
#pragma unroll
                    for (int k2 = 0; k2 < 5; k2++) {
                        float w = W0[i * 5 + k2];
#pragma unroll
                        for (int j = 0; j < 7; j++)
                            accA[j] = fmaf(w, win[j + k2], accA[j]);
                    }
                }
#pragma unroll
                for (int i = 0; i < 8; i++) {        // channel B
                    const float* row = rows1 + i * STR2;
#pragma unroll
                    for (int q = 0; q < 11; q++)
                        win[q] = (q < 7 || base + q < 140) ? row[base + q] : 0.f;
#pragma unroll
                    for (int k2 = 0; k2 < 5; k2++) {
                        float w = W1[i * 5 + k2];
#pragma unroll
                        for (int j = 0; j < 7; j++)
                            accB[j] = fmaf(w, win[j + k2], accB[j]);
                    }
                }
#pragma unroll
                for (int j = 0; j < 7; j++) {
                    if (j < nn) {
                        float r = (accA[j] + bA) + (accB[j] + bB);  // fold after channels
                        int p = base + j;
                        unsigned long long cand =
                            ((unsigned long long)fkey(r) << 32) | (unsigned)(~(unsigned)p);
                        if (cand > m3) {             // sorted insert (desc)
                            m3 = cand;
                            if (m3 > m2) { unsigned long long t = m2; m2 = m3; m3 = t;
                                if (m2 > m1) { t = m1; m1 = m2; m2 = t;
                                    if (m1 > m0) { t = m0; m0 = m1; m1 = t; } } }
                        }
                    }
                }
            }

            // Merge the 8 chunk top-4 lists (desc sorted) -> channel top-4
#pragma unroll
            for (int d = 1; d <= 4; d <<= 1) {
                unsigned long long b0v = __shfl_xor_sync(FULL, m0, d);
                unsigned long long b1v = __shfl_xor_sync(FULL, m1, d);
                unsigned long long b2v = __shfl_xor_sync(FULL, m2, d);
                unsigned long long b3v = __shfl_xor_sync(FULL, m3, d);
                unsigned long long t0v = umax64(m0, b3v);
                unsigned long long t1v = umax64(m1, b2v);
                unsigned long long t2v = umax64(m2, b1v);
                unsigned long long t3v = umax64(m3, b0v);
                unsigned long long s0 = umax64(t0v, t2v), s2 = umin64(t0v, t2v);
                unsigned long long s1 = umax64(t1v, t3v), s3 = umin64(t1v, t3v);
                m0 = umax64(s0, s1); m1 = umin64(s0, s1);
                m2 = umax64(s2, s3); m3 = umin64(s2, s3);
            }

            // Sort winners by original index (low32 = ~p: desc-by-low32 ==
            // ascending p). 5-CE network keyed on low 32 bits; chunks 0..3 emit.
            if (chunk < 4) {
                unsigned long long a0 = m0, a1 = m1, a2 = m2, a3 = m3, t;
                if ((unsigned)a0 < (unsigned)a1) { t = a0; a0 = a1; a1 = t; }
                if ((unsigned)a2 < (unsigned)a3) { t = a2; a2 = a3; a3 = t; }
                if ((unsigned)a0 < (unsigned)a2) { t = a0; a0 = a2; a2 = t; }
                if ((unsigned)a1 < (unsigned)a3) { t = a1; a1 = a3; a3 = t; }
                if ((unsigned)a1 < (unsigned)a2) { t = a1; a1 = a2; a2 = t; }
                unsigned long long sel = (chunk == 0) ? a0 : (chunk == 1) ? a1
                                       : (chunk == 2) ? a2 : a3;
                g_T2[b * 1024 + ci2_g * 4 + chunk] = tanh_fast(funkey((unsigned)(sel >> 32)));
            }
        }
        __syncthreads();   // protect sm_in/sm_A before next item's writes
    }
}

// ---------------------------------------------------------------------------
// FC (1024 -> 6) per batch. grid = 512, block = 192 (warp per class).
// ---------------------------------------------------------------------------
__global__ void __launch_bounds__(192) dcnn_fc(
    const float* __restrict__ fcw, const float* __restrict__ fcb,
    float* __restrict__ out)
{
    const int b = blockIdx.x, lane = threadIdx.x & 31, wid = threadIdx.x >> 5;
    const float* t2 = g_T2 + b * 1024;
    float s = 0.f;
    for (int d = lane; d < 1024; d += 32)
        s = fmaf(fcw[wid * 1024 + d], t2[d], s);
#pragma unroll
    for (int o = 16; o; o >>= 1) s += __shfl_xor_sync(FULL, s, o);
    if (lane == 0) out[b * 6 + wid] = s + fcb[wid];
}

extern "C" void kernel_launch(void* const* d_in, const int* in_sizes, int n_in,
                              void* d_out, int out_size) {
    const int*   x   = (const int*)d_in[0];
    const float* emb = (const float*)d_in[1];
    const float* w1  = (const float*)d_in[2];
    const float* b1  = (const float*)d_in[3];
    const float* w2  = (const float*)d_in[4];
    const float* b2  = (const float*)d_in[5];
    const float* fcw = (const float*)d_in[6];
    const float* fcb = (const float*)d_in[7];
    float* out = (float*)d_out;

    dcnn_main<<<NWORKERS, NTHREADS, SMEM_BYTES>>>(x, emb, w1, b1, w2, b2);
    dcnn_fc<<<512, 192>>>(fcw, fcb, out);
}

// round 13
// speedup vs baseline: 1.0634x; 1.0634x over previous
#include <cuda_runtime.h>

#define FULL 0xffffffffu

static constexpr int S = 256;
static constexpr int STR1 = 269;            // padded emb row: 6 + 256 + 6 (+1 spare)
static constexpr int L1_LEN = 262, K1 = 131;
static constexpr int STR2 = 140;            // padded A row: 4 + 131 + 4 (+1 spare)
static constexpr int NTHREADS = 256;
static constexpr int NWORKERS = 152 * 4;    // persistent grid: 4 CTAs/SM on 152 SMs
static constexpr int NITEMS = 512 * 8;      // item = (batch, 2-rpp half-slice)

static constexpr int ROWS_IN = 8;                       // emb rows per item
static constexpr int ROWS_A  = 32;                      // A rows per item
static constexpr int OFF_A  = ROWS_IN * STR1;           // 2152 floats
static constexpr int SMEM_FLOATS = OFF_A + ROWS_A * STR2;   // 6632
static constexpr int SMEM_BYTES  = SMEM_FLOATS * 4;         // 26528 B -> 4 CTAs/SM

__device__ float g_T2[512 * 1024];          // cross-kernel feature scratch

// Monotone float -> uint key (total order). Inverse restores the exact float.
__device__ __forceinline__ unsigned fkey(float f) {
    unsigned b = __float_as_uint(f);
    return (b & 0x80000000u) ? ~b : (b | 0x80000000u);
}
__device__ __forceinline__ float funkey(unsigned u) {
    unsigned b = (u & 0x80000000u) ? (u & 0x7fffffffu) : ~u;
    return __uint_as_float(b);
}

// Fast tanh: abs error ~1e-6 (applied only AFTER selection -> no selection impact)
__device__ __forceinline__ float tanh_fast(float x) {
    float ax = fabsf(x);
    float t = __expf(-2.f * ax);
    float r = __fdividef(1.f - t, 1.f + t);
    return copysignf(r, x);
}

__device__ __forceinline__ int iscan(int v, int lane) {
#pragma unroll
    for (int d = 1; d < 32; d <<= 1) {
        int n = __shfl_up_sync(FULL, v, d);
        if (lane >= d) v += n;
    }
    return v;
}

__device__ __forceinline__ unsigned long long umax64(unsigned long long a, unsigned long long b) { return a > b ? a : b; }
__device__ __forceinline__ unsigned long long umin64(unsigned long long a, unsigned long long b) { return a < b ? a : b; }

// Warp-collective order-preserving top-k on keys u[] (blocked across lanes,
// invalid slots key 0). Writes k tanh'd values in original index order;
// jax.lax.top_k tie semantics (earliest index). 2-bit radix bisection with
// packed counts and early exit on exact separation.
template <int NV>
__device__ __forceinline__ void topk_write_keys(const unsigned* u, int k, float* outrow, int lane) {
    unsigned thr = 0;
    bool clean = false;
#pragma unroll 1
    for (int bit = 31; bit >= 1; bit -= 2) {
        unsigned c1 = thr | (1u << (bit - 1));
        unsigned c2 = thr | (2u << (bit - 1));
        unsigned c3 = thr | (3u << (bit - 1));
        unsigned p = 0;
#pragma unroll
        for (int j = 0; j < NV; j++) {
            p += (u[j] >= c1);
            p += (u[j] >= c2) ? 1024u : 0u;
            p += (u[j] >= c3) ? (1024u * 1024u) : 0u;
        }
        p = __reduce_add_sync(FULL, p);
        int n1 = p & 1023, n2 = (p >> 10) & 1023, n3 = p >> 20;
        int cc;
        if (n3 >= k)      { thr = c3; cc = n3; }
        else if (n2 >= k) { thr = c2; cc = n2; }
        else if (n1 >= k) { thr = c1; cc = n1; }
        else              { cc = -1; }
        if (cc == k) { clean = true; break; }
    }

    if (clean) {
        int kc = 0;
#pragma unroll
        for (int j = 0; j < NV; j++) kc += (u[j] >= thr);
        int pos = iscan(kc, lane) - kc;
#pragma unroll
        for (int j = 0; j < NV; j++)
            if (u[j] >= thr) outrow[pos++] = tanh_fast(funkey(u[j]));
        return;
    }

    // Full-resolution tie path: thr is the exact k-th largest key.
    int gt = 0, eq = 0;
#pragma unroll
    for (int j = 0; j < NV; j++) { gt += (u[j] > thr); eq += (u[j] == thr); }
    int gt_tot = __reduce_add_sync(FULL, gt);
    int extra = k - gt_tot;
    int eq_excl = iscan(eq, lane) - eq;
    int myq = extra - eq_excl;
    myq = myq < 0 ? 0 : (myq > eq ? eq : myq);
    int kc = gt + myq;
    int pos = iscan(kc, lane) - kc;
    int used = 0;
#pragma unroll
    for (int j = 0; j < NV; j++) {
        bool keep = (u[j] > thr);
        if (!keep && u[j] == thr && used < myq) { keep = true; used++; }
        if (keep) outrow[pos++] = tanh_fast(funkey(u[j]));
    }
}

// ---------------------------------------------------------------------------
// Main kernel: persistent workers. grid = 608, block = 256.
// Item it = (b, h): b = it>>3, h = it&7. Covers rpp in {2h, 2h+1}:
//   emb rows [8h, 8h+8), conv1-fold channels [32h, 32h+32),
//   conv2-fold channels [32h, 32h+32).
// ---------------------------------------------------------------------------
__global__ void __launch_bounds__(NTHREADS, 4) dcnn_main(
    const int* __restrict__ x, const float* __restrict__ emb,
    const float* __restrict__ w1, const float* __restrict__ b1,
    const float* __restrict__ w2, const float* __restrict__ b2)
{
    extern __shared__ float sm[];
    float* sm_in = sm;            // [8][269]  padded embedded input slice
    float* sm_A  = sm + OFF_A;    // [32][140] padded layer-1 output slice

    const int tid = threadIdx.x, lane = tid & 31, wid = tid >> 5;

#pragma unroll 1
    for (int it = blockIdx.x; it < NITEMS; it += NWORKERS) {
        const int b = it >> 3, h = it & 7;

        // ---- zero ONLY the pad cells (conv zero-padding) ----
        for (int i = tid; i < 392; i += NTHREADS) {
            if (i < 104) {                       // sm_in pads: cols 0..5, 262..268
                int r = i / 13, c = i % 13;
                sm_in[r * STR1 + (c < 6 ? c : 256 + c)] = 0.f;
            } else {                             // sm_A pads: cols 0..3, 135..139
                int j = i - 104;
                int r = j / 9, c = j % 9;
                sm_A[r * STR2 + (c < 4 ? c : 131 + c)] = 0.f;
            }
        }

        // ---- embedding gather for this slice, transposed, padded by 6 ----
        const int* xb = x + b * S;
        const int dbase = 8 * h;
        for (int i = tid; i < S * ROWS_IN; i += NTHREADS) {
            int s = i >> 3, dl = i & 7;
            sm_in[dl * STR1 + 6 + s] = emb[(long)xb[s] * 64 + dbase + dl];
        }
        __syncthreads();

        // ---- Phase 2: conv1 (K=7) + fold(pairs) + top-131 + tanh ----
        // Warp handles 4 local channels; staging arrays reloaded PER CHANNEL so
        // they are dead before topk (no live range across the call -> no spills).
        // Association matches XLA: complete ascending-k chain per conv channel,
        // bias per channel, fold adds the two finished results.
#pragma unroll 1
        for (int fj = 0; fj < 4; fj++) {
            const int cl   = wid * 4 + fj;           // local folded channel 0..31
            const int rp_l = cl >> 3, f = cl & 7;
            const int rp_g = 4 * h + rp_l;
            const int o0 = 2 * rp_g * 8 + f, o1 = o0 + 8;
            float wA[7], wB[7];
#pragma unroll
            for (int k = 0; k < 7; k++) { wA[k] = w1[o0 * 7 + k]; wB[k] = w1[o1 * 7 + k]; }
            const float bA = b1[o0], bB = b1[o1];
            const float* inA = sm_in + (2 * rp_l) * STR1;
            const float* inB = inA + STR1;

            const int t0 = lane * 9;                 // blocked: preserves index order
            float a[15], bbv[15];
#pragma unroll
            for (int i = 0; i < 15; i++) {
                int idx = t0 + i; bool ok = idx < 268;
                a[i]   = ok ? inA[idx] : 0.f;
                bbv[i] = ok ? inB[idx] : 0.f;
            }
            unsigned u[9];
#pragma unroll
            for (int j = 0; j < 9; j++) {
                float sA = 0.f, sB = 0.f;
#pragma unroll
                for (int k = 0; k < 7; k++) {        // two independent ascending chains
                    sA = fmaf(wA[k], a[j + k], sA);
                    sB = fmaf(wB[k], bbv[j + k], sB);
                }
                float acc = (sA + bA) + (sB + bB);   // fold after completed channels
                u[j] = (t0 + j < L1_LEN) ? fkey(acc) : 0u;
            }
            topk_write_keys<9>(u, K1, sm_A + cl * STR2 + 4, lane);
        }
        __syncthreads();

        // ---- Phase 3: conv2 (K=5) + fold + top-4 + tanh ----
        // Thread-per-(channel, chunk): 32 channels x 8 chunks of 17 (last 16),
        // processed in 6-wide position blocks (6+6+5: 94% slot efficiency).
        {
            const int ci2_l = (wid << 2) | (lane >> 3);   // 0..31
            const int chunk = lane & 7;                    // 0..7
            const int rpp_l = ci2_l >> 4, f2 = ci2_l & 15;
            const int rpp_g = 2 * h + rpp_l;
            const int ci2_g = rpp_g * 16 + f2;
            const int o0 = 2 * rpp_g * 16 + f2, o1 = o0 + 16;
            const float bA = b2[o0], bB = b2[o1];
            const float* W0 = w2 + o0 * 40;
            const float* W1 = w2 + o1 * 40;
            const float* rows0 = sm_A + (16 * rpp_l) * STR2;
            const float* rows1 = rows0 + 8 * STR2;

            const int p0 = chunk * 17;
            const int np = (chunk == 7) ? 16 : 17;

            unsigned long long m0 = 0, m1 = 0, m2 = 0, m3 = 0;

#pragma unroll 1
            for (int pb = 0; pb < 17; pb += 6) {
                const int base = p0 + pb;
                const int nn = min(6, np - pb);
                float accA[6] = {0, 0, 0, 0, 0, 0};
                float accB[6] = {0, 0, 0, 0, 0, 0};
                float win[10];
#pragma unroll
                for (int i = 0; i < 8; i++) {        // channel A: (i asc, k2 asc) chain
                    const float* row = rows0 + i * STR2;
#pragma unroll
                    for (int q = 0; q < 9; q++) win[q] = row[base + q];
                    win[9] = (base + 9 < STR2) ? row[base + 9] : 0.f;
#pragma unroll
                    for (int k2 = 0; k2 < 5; k2++) {
                        float w = W0[i * 5 + k2];
#pragma unroll
                        for (int j = 0; j < 6; j++)
                            accA[j] = fmaf(w, win[j + k2], accA[j]);
                    }
                }
#pragma unroll
                for (int i = 0; i < 8; i++) {        // channel B
                    const float* row = rows1 + i * STR2;
#pragma unroll
                    for (int q = 0; q < 9; q++) win[q] = row[base + q];
                    win[9] = (base + 9 < STR2) ? row[base + 9] : 0.f;
#pragma unroll
                    for (int k2 = 0; k2 < 5; k2++) {
                        float w = W1[i * 5 + k2];
#pragma unroll
                        for (int j = 0; j < 6; j++)
                            accB[j] = fmaf(w, win[j + k2], accB[j]);
                    }
                }
#pragma unroll
                for (int j = 0; j < 6; j++) {
                    if (j < nn) {
                        float r = (accA[j] + bA) + (accB[j] + bB);  // fold after channels
                        int p = base + j;
                        unsigned long long cand =
                            ((unsigned long long)fkey(r) << 32) | (unsigned)(~(unsigned)p);
                        if (cand > m3) {             // sorted insert (desc)
                            m3 = cand;
                            if (m3 > m2) { unsigned long long t = m2; m2 = m3; m3 = t;
                                if (m2 > m1) { t = m1; m1 = m2; m2 = t;
                                    if (m1 > m0) { t = m0; m0 = m1; m1 = t; } } }
                        }
                    }
                }
            }

            // Merge the 8 chunk top-4 lists (desc sorted) -> channel top-4
#pragma unroll
            for (int d = 1; d <= 4; d <<= 1) {
                unsigned long long b0v = __shfl_xor_sync(FULL, m0, d);
                unsigned long long b1v = __shfl_xor_sync(FULL, m1, d);
                unsigned long long b2v = __shfl_xor_sync(FULL, m2, d);
                unsigned long long b3v = __shfl_xor_sync(FULL, m3, d);
                unsigned long long t0v = umax64(m0, b3v);
                unsigned long long t1v = umax64(m1, b2v);
                unsigned long long t2v = umax64(m2, b1v);
                unsigned long long t3v = umax64(m3, b0v);
                unsigned long long s0 = umax64(t0v, t2v), s2 = umin64(t0v, t2v);
                unsigned long long s1 = umax64(t1v, t3v), s3 = umin64(t1v, t3v);
                m0 = umax64(s0, s1); m1 = umin64(s0, s1);
                m2 = umax64(s2, s3); m3 = umin64(s2, s3);
            }

            // Sort winners by original index (low32 = ~p: desc-by-low32 ==
            // ascending p). 5-CE network keyed on low 32 bits; chunks 0..3 emit.
            if (chunk < 4) {
                unsigned long long a0 = m0, a1 = m1, a2 = m2, a3 = m3, t;
                if ((unsigned)a0 < (unsigned)a1) { t = a0; a0 = a1; a1 = t; }
                if ((unsigned)a2 < (unsigned)a3) { t = a2; a2 = a3; a3 = t; }
                if ((unsigned)a0 < (unsigned)a2) { t = a0; a0 = a2; a2 = t; }
                if ((unsigned)a1 < (unsigned)a3) { t = a1; a1 = a3; a3 = t; }
                if ((unsigned)a1 < (unsigned)a2) { t = a1; a1 = a2; a2 = t; }
                unsigned long long sel = (chunk == 0) ? a0 : (chunk == 1) ? a1
                                       : (chunk == 2) ? a2 : a3;
                g_T2[b * 1024 + ci2_g * 4 + chunk] = tanh_fast(funkey((unsigned)(sel >> 32)));
            }
        }
        __syncthreads();   // protect sm_in/sm_A before next item's writes
    }
}

// ---------------------------------------------------------------------------
// FC (1024 -> 6) per batch. grid = 512, block = 192 (warp per class).
// ---------------------------------------------------------------------------
__global__ void __launch_bounds__(192) dcnn_fc(
    const float* __restrict__ fcw, const float* __restrict__ fcb,
    float* __restrict__ out)
{
    const int b = blockIdx.x, lane = threadIdx.x & 31, wid = threadIdx.x >> 5;
    const float* t2 = g_T2 + b * 1024;
    float s = 0.f;
    for (int d = lane; d < 1024; d += 32)
        s = fmaf(fcw[wid * 1024 + d], t2[d], s);
#pragma unroll
    for (int o = 16; o; o >>= 1) s += __shfl_xor_sync(FULL, s, o);
    if (lane == 0) out[b * 6 + wid] = s + fcb[wid];
}

extern "C" void kernel_launch(void* const* d_in, const int* in_sizes, int n_in,
                              void* d_out, int out_size) {
    const int*   x   = (const int*)d_in[0];
    const float* emb = (const float*)d_in[1];
    const float* w1  = (const float*)d_in[2];
    const float* b1  = (const float*)d_in[3];
    const float* w2  = (const float*)d_in[4];
    const float* b2  = (const float*)d_in[5];
    const float* fcw = (const float*)d_in[6];
    const float* fcb = (const float*)d_in[7];
    float* out = (float*)d_out;

    dcnn_main<<<NWORKERS, NTHREADS, SMEM_BYTES>>>(x, emb, w1, b1, w2, b2);
    dcnn_fc<<<512, 192>>>(fcw, fcb, out);
}

// round 15
// speedup vs baseline: 1.1814x; 1.1109x over previous
#include <cuda_runtime.h>

#define FULL 0xffffffffu

static constexpr int S = 256;
static constexpr int STR1P = 295;           // padded emb row: 6 + 256 + 33 zero-tail
static constexpr int L1_LEN = 262, K1 = 131;
static constexpr int STR2P = 142;           // padded A row: 4 + 131 + 7 zero-tail (even!)
static constexpr int NTHREADS = 256;
static constexpr int NCTA_PER_B = 4;

static constexpr int ROWS_IN = 16;          // emb rows per CTA
static constexpr int ROWS_A  = 64;          // A rows per CTA
static constexpr int OFF_A  = ROWS_IN * STR1P;              // 4720 floats (even)
static constexpr int SMEM_FLOATS = OFF_A + ROWS_A * STR2P;  // 13808
static constexpr int SMEM_BYTES  = SMEM_FLOATS * 4;         // 55232 B -> 4 CTAs/SM

static constexpr int PAD_IN = 39;           // pad cells per sm_in row (6 + 33)
static constexpr int PAD_A  = 11;           // pad cells per sm_A row (4 + 7)
static constexpr int NPAD_IN = ROWS_IN * PAD_IN;            // 624
static constexpr int NPAD    = NPAD_IN + ROWS_A * PAD_A;    // 1328

__device__ float g_T2[512 * 1024];          // cross-kernel feature scratch

// Monotone float -> uint key (total order). Inverse restores the exact float.
__device__ __forceinline__ unsigned fkey(float f) {
    unsigned b = __float_as_uint(f);
    return (b & 0x80000000u) ? ~b : (b | 0x80000000u);
}
__device__ __forceinline__ float funkey(unsigned u) {
    unsigned b = (u & 0x80000000u) ? (u & 0x7fffffffu) : ~u;
    return __uint_as_float(b);
}

// Fast tanh: abs error ~1e-6 (applied only AFTER selection -> no selection impact)
__device__ __forceinline__ float tanh_fast(float x) {
    float ax = fabsf(x);
    float t = __expf(-2.f * ax);
    float r = __fdividef(1.f - t, 1.f + t);
    return copysignf(r, x);
}

__device__ __forceinline__ int iscan(int v, int lane) {
#pragma unroll
    for (int d = 1; d < 32; d <<= 1) {
        int n = __shfl_up_sync(FULL, v, d);
        if (lane >= d) v += n;
    }
    return v;
}

__device__ __forceinline__ unsigned long long umax64(unsigned long long a, unsigned long long b) { return a > b ? a : b; }
__device__ __forceinline__ unsigned long long umin64(unsigned long long a, unsigned long long b) { return a < b ? a : b; }

// Warp-collective order-preserving top-k on keys u[] (blocked across lanes,
// invalid slots key 0). Writes k tanh'd values in original index order;
// jax.lax.top_k tie semantics (earliest index). 2-bit radix bisection with
// packed counts and early exit on exact separation.
template <int NV>
__device__ __forceinline__ void topk_write_keys(const unsigned* u, int k, float* outrow, int lane) {
    unsigned thr = 0;
    bool clean = false;
#pragma unroll 1
    for (int bit = 31; bit >= 1; bit -= 2) {
        unsigned c1 = thr | (1u << (bit - 1));
        unsigned c2 = thr | (2u << (bit - 1));
        unsigned c3 = thr | (3u << (bit - 1));
        unsigned p = 0;
#pragma unroll
        for (int j = 0; j < NV; j++) {
            p += (u[j] >= c1);
            p += (u[j] >= c2) ? 1024u : 0u;
            p += (u[j] >= c3) ? (1024u * 1024u) : 0u;
        }
        p = __reduce_add_sync(FULL, p);
        int n1 = p & 1023, n2 = (p >> 10) & 1023, n3 = p >> 20;
        int cc;
        if (n3 >= k)      { thr = c3; cc = n3; }
        else if (n2 >= k) { thr = c2; cc = n2; }
        else if (n1 >= k) { thr = c1; cc = n1; }
        else              { cc = -1; }
        if (cc == k) { clean = true; break; }
    }

    if (clean) {
        int kc = 0;
#pragma unroll
        for (int j = 0; j < NV; j++) kc += (u[j] >= thr);
        int pos = iscan(kc, lane) - kc;
#pragma unroll
        for (int j = 0; j < NV; j++)
            if (u[j] >= thr) outrow[pos++] = tanh_fast(funkey(u[j]));
        return;
    }

    // Full-resolution tie path: thr is the exact k-th largest key.
    int gt = 0, eq = 0;
#pragma unroll
    for (int j = 0; j < NV; j++) { gt += (u[j] > thr); eq += (u[j] == thr); }
    int gt_tot = __reduce_add_sync(FULL, gt);
    int extra = k - gt_tot;
    int eq_excl = iscan(eq, lane) - eq;
    int myq = extra - eq_excl;
    myq = myq < 0 ? 0 : (myq > eq ? eq : myq);
    int kc = gt + myq;
    int pos = iscan(kc, lane) - kc;
    int used = 0;
#pragma unroll
    for (int j = 0; j < NV; j++) {
        bool keep = (u[j] > thr);
        if (!keep && u[j] == thr && used < myq) { keep = true; used++; }
        if (keep) outrow[pos++] = tanh_fast(funkey(u[j]));
    }
}

// ---------------------------------------------------------------------------
// Main kernel: per-(batch, slice-group) CTA. grid = 512*4, block = 256.
// Covers rpp in [4*sgrp, 4*sgrp+4): emb rows [16sgrp,16sgrp+16),
// conv1-fold channels [64sgrp,64sgrp+64), conv2-fold channels same range.
// ---------------------------------------------------------------------------
__global__ void __launch_bounds__(NTHREADS, 4) dcnn_main(
    const int* __restrict__ x, const float* __restrict__ emb,
    const float* __restrict__ w1, const float* __restrict__ b1,
    const float* __restrict__ w2, const float* __restrict__ b2)
{
    extern __shared__ float sm[];
    float* sm_in = sm;            // [16][295] padded embedded input slice
    float* sm_A  = sm + OFF_A;    // [64][142] padded layer-1 output slice

    const int tid = threadIdx.x, lane = tid & 31, wid = tid >> 5;
    const int b = blockIdx.x >> 2, sgrp = blockIdx.x & 3;

    // ---- zero ONLY the pad cells (conv zero-padding + unguarded-read tails) ----
    for (int i = tid; i < NPAD; i += NTHREADS) {
        if (i < NPAD_IN) {                   // sm_in pads: cols [0,6) U [262,295)
            int r = i / PAD_IN, c = i % PAD_IN;
            sm_in[r * STR1P + (c < 6 ? c : 256 + c)] = 0.f;
        } else {                             // sm_A pads: cols [0,4) U [135,142)
            int j = i - NPAD_IN;
            int r = j / PAD_A, c = j % PAD_A;
            sm_A[r * STR2P + (c < 4 ? c : 131 + c)] = 0.f;
        }
    }

    // ---- embedding gather for this slice, transposed, padded by 6 ----
    const int* xb = x + b * S;
    const int dbase = 16 * sgrp;
    for (int i = tid; i < S * ROWS_IN; i += NTHREADS) {
        int s = i >> 4, dl = i & 15;
        sm_in[dl * STR1P + 6 + s] = emb[(long)xb[s] * 64 + dbase + dl];
    }
    __syncthreads();

    // ---- Phase 2: conv1 (K=7) + fold(pairs) + top-131 + tanh ----
    // Association matches XLA: complete ascending-k chain per conv channel,
    // bias per channel, fold adds the two finished results. Staging reads are
    // UNGUARDED (rows zero-padded to idx 294; lane31 reads up to 293).
#pragma unroll 1
    for (int cl = wid; cl < 64; cl += 8) {
        int ci = 64 * sgrp + cl;                    // global folded channel
        int rp = ci >> 3, f = ci & 7;
        int o0 = (2 * rp) * 8 + f, o1 = o0 + 8;
        float wA[7], wB[7];
#pragma unroll
        for (int k = 0; k < 7; k++) { wA[k] = w1[o0 * 7 + k]; wB[k] = w1[o1 * 7 + k]; }
        float bA = b1[o0], bB = b1[o1];
        const float* pA = sm_in + (2 * (cl >> 3)) * STR1P + lane * 9;
        const float* pB = pA + STR1P;

        const int t0 = lane * 9;                    // blocked: preserves index order
        float a[15], bbv[15];
#pragma unroll
        for (int i = 0; i < 15; i++) { a[i] = pA[i]; bbv[i] = pB[i]; }

        unsigned u[9];
#pragma unroll
        for (int j = 0; j < 9; j++) {
            float sA = 0.f, sB = 0.f;
#pragma unroll
            for (int k = 0; k < 7; k++) {           // two independent ascending chains
                sA = fmaf(wA[k], a[j + k], sA);
                sB = fmaf(wB[k], bbv[j + k], sB);
            }
            float acc = (sA + bA) + (sB + bB);      // fold after completed channels
            u[j] = (t0 + j < L1_LEN) ? fkey(acc) : 0u;
        }
        topk_write_keys<9>(u, K1, sm_A + cl * STR2P + 4, lane);
    }
    __syncthreads();

    // ---- Phase 3: conv2 (K=5) + fold + top-4 + tanh ----
    // Thread-per-(channel, chunk): 64 channels x 4 chunks of 34 (last 33).
    // Position blocks of 6 with EVEN base -> window loads are aligned float2
    // (5 x LDS.64 per row, unguarded: rows zero-padded to col 141).
    {
        const int rpp_l = wid >> 1;                 // 0..3 local slice
        const int rpp   = 4 * sgrp + rpp_l;
        const int f2    = (wid & 1) * 8 + (lane >> 2);
        const int chunk = lane & 3;
        const int ci2   = rpp * 16 + f2;            // global conv2-fold channel
        const int o0    = (2 * rpp) * 16 + f2, o1 = o0 + 16;
        const float bA  = b2[o0], bB = b2[o1];
        const float* W0 = w2 + o0 * 40;
        const float* W1 = w2 + o1 * 40;
        const float* rows0 = sm_A + (16 * rpp_l) * STR2P;
        const float* rows1 = rows0 + 8 * STR2P;

        const int p0 = chunk * 34;                  // even
        const int np = (chunk == 3) ? 33 : 34;

        unsigned long long m0 = 0, m1 = 0, m2 = 0, m3 = 0;

#pragma unroll 1
        for (int pb = 0; pb < 34; pb += 6) {        // 6 blocks: 5 full + remainder
            const int base = p0 + pb;               // even -> float2 aligned
            const int nn = min(6, np - pb);
            float accA[6] = {0, 0, 0, 0, 0, 0};
            float accB[6] = {0, 0, 0, 0, 0, 0};
            float win[10];
#pragma unroll
            for (int i = 0; i < 8; i++) {           // channel A: (i asc, k2 asc) chain
                const float2* r2 = (const float2*)(rows0 + i * STR2P + base);
#pragma unroll
                for (int q = 0; q < 5; q++) {
                    float2 v = r2[q];
                    win[2 * q] = v.x; win[2 * q + 1] = v.y;
                }
#pragma unroll
                for (int k2 = 0; k2 < 5; k2++) {
                    float w = W0[i * 5 + k2];
#pragma unroll
                    for (int j = 0; j < 6; j++)
                        accA[j] = fmaf(w, win[j + k2], accA[j]);
                }
            }
#pragma unroll
            for (int i = 0; i < 8; i++) {           // channel B
                const float2* r2 = (const float2*)(rows1 + i * STR2P + base);
#pragma unroll
                for (int q = 0; q < 5; q++) {
                    float2 v = r2[q];
                    win[2 * q] = v.x; win[2 * q + 1] = v.y;
                }
#pragma unroll
                for (int k2 = 0; k2 < 5; k2++) {
                    float w = W1[i * 5 + k2];
#pragma unroll
                    for (int j = 0; j < 6; j++)
                        accB[j] = fmaf(w, win[j + k2], accB[j]);
                }
            }
#pragma unroll
            for (int j = 0; j < 6; j++) {
                if (j < nn) {
                    float r = (accA[j] + bA) + (accB[j] + bB);  // fold after channels
                    int p = base + j;
                    unsigned long long cand =
                        ((unsigned long long)fkey(r) << 32) | (unsigned)(~(unsigned)p);
                    if (cand > m3) {                 // sorted insert (desc)
                        m3 = cand;
                        if (m3 > m2) { unsigned long long t = m2; m2 = m3; m3 = t;
                            if (m2 > m1) { t = m1; m1 = m2; m2 = t;
                                if (m1 > m0) { t = m0; m0 = m1; m1 = t; } } }
                    }
                }
            }
        }

        // Merge the 4 chunk top-4 lists (desc sorted) -> channel top-4
#pragma unroll
        for (int d = 1; d <= 2; d <<= 1) {
            unsigned long long b0v = __shfl_xor_sync(FULL, m0, d);
            unsigned long long b1v = __shfl_xor_sync(FULL, m1, d);
            unsigned long long b2v = __shfl_xor_sync(FULL, m2, d);
            unsigned long long b3v = __shfl_xor_sync(FULL, m3, d);
            unsigned long long t0v = umax64(m0, b3v);
            unsigned long long t1v = umax64(m1, b2v);
            unsigned long long t2v = umax64(m2, b1v);
            unsigned long long t3v = umax64(m3, b0v);
            unsigned long long s0 = umax64(t0v, t2v), s2 = umin64(t0v, t2v);
            unsigned long long s1 = umax64(t1v, t3v), s3 = umin64(t1v, t3v);
            m0 = umax64(s0, s1); m1 = umin64(s0, s1);
            m2 = umax64(s2, s3); m3 = umin64(s2, s3);
        }

        // Sort winners by original index (low32 = ~p: desc-by-low32 ==
        // ascending p). 5-CE network keyed on low 32 bits; each chunk emits one.
        {
            unsigned long long a0 = m0, a1 = m1, a2 = m2, a3 = m3, t;
            if ((unsigned)a0 < (unsigned)a1) { t = a0; a0 = a1; a1 = t; }
            if ((unsigned)a2 < (unsigned)a3) { t = a2; a2 = a3; a3 = t; }
            if ((unsigned)a0 < (unsigned)a2) { t = a0; a0 = a2; a2 = t; }
            if ((unsigned)a1 < (unsigned)a3) { t = a1; a1 = a3; a3 = t; }
            if ((unsigned)a1 < (unsigned)a2) { t = a1; a1 = a2; a2 = t; }
            unsigned long long sel = (chunk == 0) ? a0 : (chunk == 1) ? a1
                                   : (chunk == 2) ? a2 : a3;
            g_T2[b * 1024 + ci2 * 4 + chunk] = tanh_fast(funkey((unsigned)(sel >> 32)));
        }
    }
}

// ---------------------------------------------------------------------------
// FC (1024 -> 6) per batch. grid = 512, block = 192 (warp per class).
// ---------------------------------------------------------------------------
__global__ void __launch_bounds__(192) dcnn_fc(
    const float* __restrict__ fcw, const float* __restrict__ fcb,
    float* __restrict__ out)
{
    const int b = blockIdx.x, lane = threadIdx.x & 31, wid = threadIdx.x >> 5;
    const float* t2 = g_T2 + b * 1024;
    float s = 0.f;
    for (int d = lane; d < 1024; d += 32)
        s = fmaf(fcw[wid * 1024 + d], t2[d], s);
#pragma unroll
    for (int o = 16; o; o >>= 1) s += __shfl_xor_sync(FULL, s, o);
    if (lane == 0) out[b * 6 + wid] = s + fcb[wid];
}

extern "C" void kernel_launch(void* const* d_in, const int* in_sizes, int n_in,
                              void* d_out, int out_size) {
    const int*   x   = (const int*)d_in[0];
    const float* emb = (const float*)d_in[1];
    const float* w1  = (const float*)d_in[2];
    const float* b1  = (const float*)d_in[3];
    const float* w2  = (const float*)d_in[4];
    const float* b2  = (const float*)d_in[5];
    const float* fcw = (const float*)d_in[6];
    const float* fcb = (const float*)d_in[7];
    float* out = (float*)d_out;

    cudaFuncSetAttribute(dcnn_main, cudaFuncAttributeMaxDynamicSharedMemorySize, SMEM_BYTES);
    dcnn_main<<<512 * NCTA_PER_B, NTHREADS, SMEM_BYTES>>>(x, emb, w1, b1, w2, b2);
    dcnn_fc<<<512, 192>>>(fcw, fcb, out);
}